// round 16
// baseline (speedup 1.0000x reference)
#include <cuda_runtime.h>
#include <cuda_fp16.h>
#include <math.h>

#define BB 2
#define NN 2048
#define DD 128
#define HH 16
#define ALLD 2048
#define BN  4096

#define BQ 64          // q rows per attention block (4 warps x 16)
#define TK 64          // keys per tile

#define KS_STR 136     // halves per K row
#define VT_STR 72      // halves per V^T row

// Scratch (zero-initialized device globals; tails beyond cnt are never
// written and therefore stay zero — guarded stores keep it that way)
__device__ __half g_xc [BN*DD];         // compacted x as half [b][j][d]
__device__ __half g_Wt [3*ALLD*DD];     // W{q,k,v}^T half [n][k], SC in Wq
__device__ __half g_Wot[DD*ALLD];       // Wo^T half [n][k]
__device__ __half g_Qc [BB*HH*NN*DD];   // compacted Q [bh][j][d], pre-scaled
__device__ __half g_Kc [BB*HH*NN*DD];   // compacted K [bh][j][d]
__device__ __half g_Vtc[BB*HH*DD*NN];   // compacted V^T [bh][d][j]
__device__ __half g_Chc[BB*NN*ALLD];    // compacted ctx [b][j][ALLD]
__device__ int    g_idx[BB*NN];         // valid-token indices
__device__ int    g_cnt[BB];

__device__ __forceinline__ unsigned h2pack(float x, float y) {
    __half2 h = __floats2half2_rn(x, y);
    return *(unsigned*)&h;
}

__device__ __forceinline__ void mma16(float* c,
                                      unsigned a0, unsigned a1, unsigned a2, unsigned a3,
                                      unsigned b0, unsigned b1) {
    asm volatile(
        "mma.sync.aligned.m16n8k16.row.col.f32.f16.f16.f32 "
        "{%0,%1,%2,%3}, {%4,%5,%6,%7}, {%8,%9}, {%0,%1,%2,%3};"
        : "+f"(c[0]), "+f"(c[1]), "+f"(c[2]), "+f"(c[3])
        : "r"(a0), "r"(a1), "r"(a2), "r"(a3), "r"(b0), "r"(b1));
}

__device__ __forceinline__ void cp16(unsigned dst, const void* src) {
    asm volatile("cp.async.cg.shared.global [%0], [%1], 16;" :: "r"(dst), "l"(src));
}

#define SCQ 0.08838834764831845f   // 1/sqrt(128)

// ---------------------------------------------------------------------------
// Kernel 0: compact valid token indices per batch. grid BB, 256 threads.
// ---------------------------------------------------------------------------
__global__ __launch_bounds__(256)
void compact_kernel(const int* __restrict__ mask)
{
    __shared__ int cnts[256];
    __shared__ int offs[256];

    const int b = blockIdx.x;
    const int t = threadIdx.x;
    const int base = t * 8;

    int mloc[8];
    int c = 0;
    #pragma unroll
    for (int i = 0; i < 8; i++) {
        mloc[i] = mask[b * NN + base + i];
        c += (mloc[i] != 0);
    }
    cnts[t] = c;
    __syncthreads();

    if (t == 0) {
        int run = 0;
        for (int i = 0; i < 256; i++) { offs[i] = run; run += cnts[i]; }
        g_cnt[b] = run;
    }
    __syncthreads();

    int o = offs[t];
    #pragma unroll
    for (int i = 0; i < 8; i++)
        if (mloc[i]) g_idx[b * NN + (o++)] = base + i;

    __syncthreads();
    const int cnt = g_cnt[b];
    for (int i = cnt + t; i < NN; i += 256) g_idx[b * NN + i] = 0;
}

// ---------------------------------------------------------------------------
// Kernel 1a: gather x into compacted xc (half). grid N_XH/256.
// ---------------------------------------------------------------------------
#define N_XH (BN*DD)

__global__ __launch_bounds__(256)
void convert_x_kernel(const float* __restrict__ x)
{
    const int idx = blockIdx.x * 256 + threadIdx.x;
    const int r = idx >> 7;
    const int d = idx & 127;
    const int b = r >> 11;
    const int j = r & 2047;
    if (j < g_cnt[b])
        g_xc[idx] = __float2half_rn(
            x[((size_t)(b * NN + g_idx[b * NN + j])) * DD + d]);
}

// ---------------------------------------------------------------------------
// Kernel 1b: smem-tiled weight transpose to half.
// blocks 0..767:   Wq/Wk/Wv [128k x 2048c] -> g_Wt[c][k]  (SCQ folded in Wq)
// blocks 768..1023: Wo [2048k x 128n]      -> g_Wot[n][k]
// 32x32 tiles, 256 threads.
// ---------------------------------------------------------------------------
__global__ __launch_bounds__(256)
void transpose_w_kernel(const float* __restrict__ Wq,
                        const float* __restrict__ Wk,
                        const float* __restrict__ Wv,
                        const float* __restrict__ Wo)
{
    __shared__ float ts[32][33];

    const int tid = blockIdx.x;
    const int tx  = threadIdx.x & 31;
    const int ty  = threadIdx.x >> 5;   // 0..7

    if (tid < 768) {
        const int proj = tid >> 8;
        const int tt   = tid & 255;
        const int k0   = (tt & 3) * 32;
        const int c0   = (tt >> 2) * 32;
        const float* W  = (proj == 0) ? Wq : (proj == 1) ? Wk : Wv;
        const float scl = (proj == 0) ? SCQ : 1.0f;
        #pragma unroll
        for (int i = 0; i < 4; i++) {
            const int row = ty + i * 8;
            ts[row][tx] = W[(size_t)(k0 + row) * ALLD + c0 + tx] * scl;
        }
        __syncthreads();
        #pragma unroll
        for (int i = 0; i < 4; i++) {
            const int r = ty + i * 8;
            g_Wt[(size_t)(proj * ALLD + c0 + r) * DD + k0 + tx] =
                __float2half_rn(ts[tx][r]);
        }
    } else {
        const int tt = tid - 768;
        const int n0 = (tt & 3) * 32;
        const int k0 = (tt >> 2) * 32;
        #pragma unroll
        for (int i = 0; i < 4; i++) {
            const int row = ty + i * 8;
            ts[row][tx] = Wo[(size_t)(k0 + row) * DD + n0 + tx];
        }
        __syncthreads();
        #pragma unroll
        for (int i = 0; i < 4; i++) {
            const int r = ty + i * 8;
            g_Wot[(size_t)(n0 + r) * ALLD + k0 + tx] =
                __float2half_rn(ts[tx][r]);
        }
    }
}

// ---------------------------------------------------------------------------
// Kernel 2: QKV projection over compacted rows (fp16 MMA).
// grid (BB*16, 48); block = 128 compacted rows x 128 cols; 256 thr, 8 warps.
// V output (proj==2) is transposed in-block and written to g_Vtc directly.
// ---------------------------------------------------------------------------
#define GQ_XS_STR 136
#define GQ_XS_BYTES (128 * GQ_XS_STR * 2)    // 34816
#define GQ_WS_BYTES (128 * GQ_XS_STR * 2)    // 34816
#define GQ_SMEM (GQ_XS_BYTES + GQ_WS_BYTES)  // 69632

__global__ __launch_bounds__(256)
void gemm_qkv_kernel(const float* __restrict__ bq,
                     const float* __restrict__ bk,
                     const float* __restrict__ bv)
{
    extern __shared__ char sm[];
    __half* xs = (__half*)sm;
    __half* ws = (__half*)(sm + GQ_XS_BYTES);

    const int b  = blockIdx.x >> 4;
    const int j0 = (blockIdx.x & 15) * 128;
    const int cnt = g_cnt[b];
    if (j0 >= cnt) return;

    const int n0 = blockIdx.y * 128;
    const int proj = n0 >> 11;
    const int h    = (n0 >> 7) & 15;

    const int t    = threadIdx.x;
    const int warp = t >> 5;            // 0..7
    const int lane = t & 31;
    const int g    = lane >> 2;
    const int tg   = lane & 3;
    const int m0   = warp * 16;         // rows 0..127

    const unsigned smu = (unsigned)__cvta_generic_to_shared(sm);

    #pragma unroll
    for (int p = 0; p < 8; p++) {
        const int c   = t + p * 256;
        const int row = c >> 4;
        const int cd  = (c & 15) * 8;
        cp16(smu + (row * GQ_XS_STR + cd) * 2,
             g_xc + ((size_t)(b * NN + j0 + row)) * DD + cd);
    }
    #pragma unroll
    for (int p = 0; p < 8; p++) {
        const int c   = t + p * 256;
        const int row = c >> 4;
        const int cd  = (c & 15) * 8;
        cp16(smu + GQ_XS_BYTES + (row * GQ_XS_STR + cd) * 2,
             g_Wt + (size_t)(n0 + row) * DD + cd);
    }
    asm volatile("cp.async.commit_group;" ::: "memory");
    asm volatile("cp.async.wait_group 0;" ::: "memory");
    __syncthreads();

    float acc[16][4];
    #pragma unroll
    for (int j = 0; j < 16; j++) { acc[j][0]=0.f; acc[j][1]=0.f; acc[j][2]=0.f; acc[j][3]=0.f; }

    #pragma unroll
    for (int s = 0; s < 8; s++) {
        const int kc = 16 * s + 2 * tg;
        const unsigned a0 = *(const unsigned*)&xs[(m0 + g)     * GQ_XS_STR + kc];
        const unsigned a1 = *(const unsigned*)&xs[(m0 + g + 8) * GQ_XS_STR + kc];
        const unsigned a2 = *(const unsigned*)&xs[(m0 + g)     * GQ_XS_STR + kc + 8];
        const unsigned a3 = *(const unsigned*)&xs[(m0 + g + 8) * GQ_XS_STR + kc + 8];
        #pragma unroll
        for (int j = 0; j < 16; j++) {
            const unsigned b0 = *(const unsigned*)&ws[(8 * j + g) * GQ_XS_STR + kc];
            const unsigned b1 = *(const unsigned*)&ws[(8 * j + g) * GQ_XS_STR + kc + 8];
            mma16(acc[j], a0, a1, a2, a3, b0, b1);
        }
    }

    const float* bias = (proj == 0) ? bq : (proj == 1) ? bk : bv;
    const int bcol = n0 & 2047;
    const int row0 = j0 + m0 + g;        // local compacted row
    const int row1 = row0 + 8;
    const int bh   = b * HH + h;

    if (proj < 2) {
        const float bscl = (proj == 0) ? SCQ : 1.0f;
        __half* dst = (proj == 0) ? g_Qc : g_Kc;
        __half* d0 = dst + ((size_t)bh * NN + row0) * DD;
        __half* d1 = dst + ((size_t)bh * NN + row1) * DD;
        const bool s0ok = row0 < cnt;
        const bool s1ok = row1 < cnt;

        #pragma unroll
        for (int j = 0; j < 16; j++) {
            const int ci = 8 * j + 2 * tg;
            const float bb0 = bias[bcol + ci]     * bscl;
            const float bb1 = bias[bcol + ci + 1] * bscl;
            if (s0ok) *(unsigned*)&d0[ci] = h2pack(acc[j][0] + bb0, acc[j][1] + bb1);
            if (s1ok) *(unsigned*)&d1[ci] = h2pack(acc[j][2] + bb0, acc[j][3] + bb1);
        }
    } else {
        // V: transpose in smem (reuse xs region), write Vtc directly.
        // Tail rows (>= cnt) come from zero xc -> acc = bias (finite); the
        // attention PV multiplies them by P==0, so unguarded writes are safe.
        __syncthreads();                  // all MMA smem reads complete
        __half* ts = (__half*)sm;         // [128 d][136 j]
        const int lr0 = m0 + g;           // local row within 128-tile
        const int lr1 = lr0 + 8;
        #pragma unroll
        for (int j = 0; j < 16; j++) {
            const int ci = 8 * j + 2 * tg;
            const float bb0 = bias[bcol + ci];
            const float bb1 = bias[bcol + ci + 1];
            ts[(ci    ) * GQ_XS_STR + lr0] = __float2half_rn(acc[j][0] + bb0);
            ts[(ci + 1) * GQ_XS_STR + lr0] = __float2half_rn(acc[j][1] + bb1);
            ts[(ci    ) * GQ_XS_STR + lr1] = __float2half_rn(acc[j][2] + bb0);
            ts[(ci + 1) * GQ_XS_STR + lr1] = __float2half_rn(acc[j][3] + bb1);
        }
        __syncthreads();

        const int d  = t >> 1;            // 0..127
        const int jh = (t & 1) * 64;
        __half* dst = g_Vtc + ((size_t)bh * DD + d) * NN + j0 + jh;
        #pragma unroll
        for (int p = 0; p < 8; p++)
            *(uint4*)&dst[p * 8] = *(const uint4*)&ts[d * GQ_XS_STR + jh + p * 8];
    }
}

// ---------------------------------------------------------------------------
// Kernel 4: flash attention over compacted q/k/v. 3 blocks/SM enforced.
// (unchanged from round 15)
// ---------------------------------------------------------------------------
#define KS_BYTES (TK * KS_STR * 2)
#define VT_BYTES (DD * VT_STR * 2)
#define SM_KS(buf)  ((buf) * KS_BYTES)
#define SM_VT(buf)  (2 * KS_BYTES + (buf) * VT_BYTES)
#define ATT_SMEM    (2 * KS_BYTES + 2 * VT_BYTES)

__global__ __launch_bounds__(128, 3)
void attn_fp16_kernel()
{
    extern __shared__ char sm[];

    const int bid = blockIdx.x;
    const int qt  = bid & 31;
    const int bh  = bid >> 5;
    const int b   = bh >> 4;
    const int n0  = qt * BQ;

    const int cnt = g_cnt[b];
    if (n0 >= cnt) return;

    const int t    = threadIdx.x;
    const int warp = t >> 5;
    const int lane = t & 31;
    const int g    = lane >> 2;
    const int tg   = lane & 3;
    const int m0   = warp * 16;

    const __half* Qc  = g_Qc  + (size_t)bh * NN * DD;
    const __half* Kc  = g_Kc  + (size_t)bh * NN * DD;
    const __half* Vtc = g_Vtc + (size_t)bh * DD * NN;

    const unsigned smu = (unsigned)__cvta_generic_to_shared(sm);

    auto stage = [&](int kt, int buf) {
        const int k0 = kt * TK;
        const unsigned ksu = smu + SM_KS(buf);
        const unsigned vtu = smu + SM_VT(buf);
        #pragma unroll
        for (int p = 0; p < 8; p++) {
            const int c   = t + p * 128;
            const int row = c >> 4;
            const int cd  = (c & 15) * 8;
            cp16(ksu + (row * KS_STR + cd) * 2, Kc + (size_t)(k0 + row) * DD + cd);
        }
        #pragma unroll
        for (int p = 0; p < 8; p++) {
            const int c   = t + p * 128;
            const int row = c >> 3;
            const int cd  = (c & 7) * 8;
            cp16(vtu + (row * VT_STR + cd) * 2, Vtc + (size_t)row * NN + k0 + cd);
        }
        asm volatile("cp.async.commit_group;" ::: "memory");
    };

    const int jr0 = n0 + m0 + g;
    const int jr1 = jr0 + 8;
    unsigned qa[8][4];
    {
        const __half* q0 = Qc + (size_t)jr0 * DD;
        const __half* q1 = Qc + (size_t)jr1 * DD;
        #pragma unroll
        for (int s = 0; s < 8; s++) {
            const int c = 16 * s + 2 * tg;
            qa[s][0] = *(const unsigned*)&q0[c];
            qa[s][1] = *(const unsigned*)&q1[c];
            qa[s][2] = *(const unsigned*)&q0[c + 8];
            qa[s][3] = *(const unsigned*)&q1[c + 8];
        }
    }

    const int NTc = (cnt + TK - 1) / TK;
    stage(0, 0);

    float o[16][4];
    #pragma unroll
    for (int j = 0; j < 16; j++) { o[j][0]=0.f; o[j][1]=0.f; o[j][2]=0.f; o[j][3]=0.f; }
    float l0 = 0.f, l1 = 0.f;

    for (int kt = 0; kt < NTc; kt++) {
        const int buf = kt & 1;
        const int k0  = kt * TK;
        asm volatile("cp.async.wait_group 0;" ::: "memory");
        __syncthreads();

        if (kt + 1 < NTc) stage(kt + 1, buf ^ 1);

        const __half* ks = (const __half*)(sm + SM_KS(buf));
        const __half* vt = (const __half*)(sm + SM_VT(buf));

        float sc[8][4];
        #pragma unroll
        for (int j = 0; j < 8; j++) { sc[j][0]=0.f; sc[j][1]=0.f; sc[j][2]=0.f; sc[j][3]=0.f; }

        #pragma unroll
        for (int s = 0; s < 8; s++) {
            const int dcol = 16 * s + 2 * tg;
            #pragma unroll
            for (int j = 0; j < 8; j++) {
                const unsigned b0 = *(const unsigned*)&ks[(8 * j + g) * KS_STR + dcol];
                const unsigned b1 = *(const unsigned*)&ks[(8 * j + g) * KS_STR + dcol + 8];
                mma16(sc[j], qa[s][0], qa[s][1], qa[s][2], qa[s][3], b0, b1);
            }
        }

        unsigned pa[4][4];
        #pragma unroll
        for (int j = 0; j < 8; j++) {
            const int ci = 8 * j + 2 * tg;
            const bool v0 = (k0 + ci)     < cnt;
            const bool v1 = (k0 + ci + 1) < cnt;
            const float e0 = v0 ? __expf(sc[j][0]) : 0.f;
            const float e1 = v1 ? __expf(sc[j][1]) : 0.f;
            const float e2 = v0 ? __expf(sc[j][2]) : 0.f;
            const float e3 = v1 ? __expf(sc[j][3]) : 0.f;
            l0 += e0 + e1;
            l1 += e2 + e3;
            const unsigned h01 = h2pack(e0, e1);
            const unsigned h23 = h2pack(e2, e3);
            const int s2 = j >> 1;
            if ((j & 1) == 0) { pa[s2][0] = h01; pa[s2][1] = h23; }
            else              { pa[s2][2] = h01; pa[s2][3] = h23; }
        }

        #pragma unroll
        for (int s2 = 0; s2 < 4; s2++) {
            const int kcol = 16 * s2 + 2 * tg;
            #pragma unroll
            for (int j2 = 0; j2 < 16; j2++) {
                const unsigned b0 = *(const unsigned*)&vt[(8 * j2 + g) * VT_STR + kcol];
                const unsigned b1 = *(const unsigned*)&vt[(8 * j2 + g) * VT_STR + kcol + 8];
                mma16(o[j2], pa[s2][0], pa[s2][1], pa[s2][2], pa[s2][3], b0, b1);
            }
        }
        __syncthreads();
    }

    l0 += __shfl_xor_sync(0xffffffffu, l0, 1);
    l0 += __shfl_xor_sync(0xffffffffu, l0, 2);
    l1 += __shfl_xor_sync(0xffffffffu, l1, 1);
    l1 += __shfl_xor_sync(0xffffffffu, l1, 2);

    const bool  val0 = jr0 < cnt;
    const bool  val1 = jr1 < cnt;
    const float inv0 = 1.0f / l0;
    const float inv1 = 1.0f / l1;
    const int   h    = bh & 15;

    __half* ctx0 = g_Chc + ((size_t)(b * NN + jr0)) * ALLD + h * DD;
    __half* ctx1 = g_Chc + ((size_t)(b * NN + jr1)) * ALLD + h * DD;
    #pragma unroll
    for (int j2 = 0; j2 < 16; j2++) {
        const int ci = 8 * j2 + 2 * tg;
        if (val0) *(unsigned*)&ctx0[ci] = h2pack(o[j2][0] * inv0, o[j2][1] * inv0);
        if (val1) *(unsigned*)&ctx1[ci] = h2pack(o[j2][2] * inv1, o[j2][3] * inv1);
    }
}

// ---------------------------------------------------------------------------
// Kernel 5: output projection over compacted ctx rows; scatter via idx.
// grid (BB*32); block = 64 compacted rows; 256 thr, 8 warps
// (warp = (row-half warp>>2) x (32-col group warp&3)).
// ---------------------------------------------------------------------------
#define GO_AS_STR 72
#define GO_AS_BYTES (64 * GO_AS_STR * 2)      // 9216
#define GO_WS_BYTES (128 * GO_AS_STR * 2)     // 18432
#define GO_SM_A(buf) ((buf) * (GO_AS_BYTES + GO_WS_BYTES))
#define GO_SM_W(buf) (GO_SM_A(buf) + GO_AS_BYTES)
#define GO_SMEM (2 * (GO_AS_BYTES + GO_WS_BYTES))

__global__ __launch_bounds__(256)
void gemm_out_kernel(const float* __restrict__ bo, float* __restrict__ out)
{
    extern __shared__ char sm[];

    const int b   = blockIdx.x >> 5;
    const int r0c = (blockIdx.x & 31) * 64;
    const int cnt = g_cnt[b];
    if (r0c >= cnt) return;

    const int t     = threadIdx.x;
    const int warp  = t >> 5;
    const int warpc = warp & 3;          // col group (32 cols)
    const int warpr = warp >> 2;         // row half (32 rows)
    const int lane  = t & 31;
    const int g     = lane >> 2;
    const int tg    = lane & 3;

    const unsigned smu = (unsigned)__cvta_generic_to_shared(sm);
    const __half* A = g_Chc + (size_t)(b * NN + r0c) * ALLD;

    auto stage = [&](int kt, int buf) {
        const int k0 = kt * 64;
        const unsigned au = smu + GO_SM_A(buf);
        const unsigned wu = smu + GO_SM_W(buf);
        #pragma unroll
        for (int p = 0; p < 2; p++) {
            const int c   = t + p * 256;
            const int row = c >> 3;          // 0..63
            const int cd  = (c & 7) * 8;
            cp16(au + (row * GO_AS_STR + cd) * 2, A + (size_t)row * ALLD + k0 + cd);
        }
        #pragma unroll
        for (int p = 0; p < 4; p++) {
            const int c   = t + p * 256;
            const int row = c >> 3;          // 0..127
            const int cd  = (c & 7) * 8;
            cp16(wu + (row * GO_AS_STR + cd) * 2, g_Wot + (size_t)row * ALLD + k0 + cd);
        }
        asm volatile("cp.async.commit_group;" ::: "memory");
    };

    stage(0, 0);

    float acc[2][4][4];
    #pragma unroll
    for (int jm = 0; jm < 2; jm++)
        #pragma unroll
        for (int jn = 0; jn < 4; jn++) {
            acc[jm][jn][0]=0.f; acc[jm][jn][1]=0.f; acc[jm][jn][2]=0.f; acc[jm][jn][3]=0.f;
        }

    for (int kt = 0; kt < 32; kt++) {
        const int buf = kt & 1;
        asm volatile("cp.async.wait_group 0;" ::: "memory");
        __syncthreads();

        if (kt + 1 < 32) stage(kt + 1, buf ^ 1);

        const __half* as = (const __half*)(sm + GO_SM_A(buf));
        const __half* ws = (const __half*)(sm + GO_SM_W(buf));

        #pragma unroll
        for (int s = 0; s < 4; s++) {
            const int kc = 16 * s + 2 * tg;
            unsigned a[2][4];
            #pragma unroll
            for (int jm = 0; jm < 2; jm++) {
                const int rbase = warpr * 32 + 16 * jm + g;
                a[jm][0] = *(const unsigned*)&as[(rbase)     * GO_AS_STR + kc];
                a[jm][1] = *(const unsigned*)&as[(rbase + 8) * GO_AS_STR + kc];
                a[jm][2] = *(const unsigned*)&as[(rbase)     * GO_AS_STR + kc + 8];
                a[jm][3] = *(const unsigned*)&as[(rbase + 8) * GO_AS_STR + kc + 8];
            }
            #pragma unroll
            for (int jn = 0; jn < 4; jn++) {
                const int n = 32 * warpc + 8 * jn + g;
                const unsigned b0 = *(const unsigned*)&ws[n * GO_AS_STR + kc];
                const unsigned b1 = *(const unsigned*)&ws[n * GO_AS_STR + kc + 8];
                #pragma unroll
                for (int jm = 0; jm < 2; jm++)
                    mma16(acc[jm][jn], a[jm][0], a[jm][1], a[jm][2], a[jm][3], b0, b1);
            }
        }
        __syncthreads();
    }

    const int* idx = g_idx + b * NN;
    #pragma unroll
    for (int jm = 0; jm < 2; jm++) {
        const int jrow0 = r0c + warpr * 32 + 16 * jm + g;
        const int jrow1 = jrow0 + 8;
        const bool ok0 = jrow0 < cnt;
        const bool ok1 = jrow1 < cnt;
        const int orow0 = ok0 ? (b * NN + idx[jrow0]) : 0;
        const int orow1 = ok1 ? (b * NN + idx[jrow1]) : 0;
        #pragma unroll
        for (int jn = 0; jn < 4; jn++) {
            const int col = 32 * warpc + 8 * jn + 2 * tg;
            const float bb0 = bo[col], bb1 = bo[col + 1];
            float2 w0, w1;
            w0.x = acc[jm][jn][0] + bb0;  w0.y = acc[jm][jn][1] + bb1;
            w1.x = acc[jm][jn][2] + bb0;  w1.y = acc[jm][jn][3] + bb1;
            if (ok0) *(float2*)&out[(size_t)orow0 * DD + col] = w0;
            if (ok1) *(float2*)&out[(size_t)orow1 * DD + col] = w1;
        }
    }
}

// ---------------------------------------------------------------------------
// Kernel 6: fill masked output rows with bias. grid 512, 256 thr.
// ---------------------------------------------------------------------------
__global__ __launch_bounds__(256)
void fill_out_kernel(const int* __restrict__ mask,
                     const float* __restrict__ bo,
                     float* __restrict__ out)
{
    const int i = blockIdx.x * 256 + threadIdx.x;
    const int total = BN * DD;
    for (int idx = i; idx < total; idx += gridDim.x * 256) {
        const int row = idx >> 7;
        if (mask[row] == 0)
            out[idx] = __ldg(&bo[idx & 127]);
    }
}

// ---------------------------------------------------------------------------
extern "C" void kernel_launch(void* const* d_in, const int* in_sizes, int n_in,
                              void* d_out, int out_size)
{
    const float* x    = (const float*)d_in[0];
    const int*   mask = (const int*)  d_in[1];
    const float* Wq   = (const float*)d_in[2];
    const float* bq   = (const float*)d_in[3];
    const float* Wk   = (const float*)d_in[4];
    const float* bk   = (const float*)d_in[5];
    const float* Wv   = (const float*)d_in[6];
    const float* bv   = (const float*)d_in[7];
    const float* Wo   = (const float*)d_in[8];
    const float* bo   = (const float*)d_in[9];
    float* out = (float*)d_out;

    compact_kernel<<<BB, 256>>>(mask);
    convert_x_kernel<<<N_XH / 256, 256>>>(x);
    transpose_w_kernel<<<1024, 256>>>(Wq, Wk, Wv, Wo);

    cudaFuncSetAttribute((const void*)gemm_qkv_kernel,
                         cudaFuncAttributeMaxDynamicSharedMemorySize, GQ_SMEM);
    gemm_qkv_kernel<<<dim3(BB * 16, 48), 256, GQ_SMEM>>>(bq, bk, bv);

    cudaFuncSetAttribute((const void*)attn_fp16_kernel,
                         cudaFuncAttributeMaxDynamicSharedMemorySize, ATT_SMEM);
    attn_fp16_kernel<<<BB * HH * 32, 128, ATT_SMEM>>>();

    cudaFuncSetAttribute((const void*)gemm_out_kernel,
                         cudaFuncAttributeMaxDynamicSharedMemorySize, GO_SMEM);
    gemm_out_kernel<<<BB * 32, 256, GO_SMEM>>>(bo, out);

    fill_out_kernel<<<512, 256>>>(mask, bo, out);
}

// round 17
// speedup vs baseline: 1.0395x; 1.0395x over previous
#include <cuda_runtime.h>
#include <cuda_fp16.h>
#include <math.h>

#define BB 2
#define NN 2048
#define DD 128
#define HH 16
#define ALLD 2048
#define BN  4096

#define BQ 64          // q rows per attention block (4 warps x 16)
#define TK 64          // keys per tile

#define KS_STR 136     // halves per K row
#define VT_STR 72      // halves per V^T row

// Scratch (zero-initialized device globals; tails beyond cnt are never
// written and therefore stay zero — guarded stores keep it that way)
__device__ __half g_xc [BN*DD];         // compacted x as half [b][j][d]
__device__ __half g_Wt [3*ALLD*DD];     // W{q,k,v}^T half [n][k], SC in Wq
__device__ __half g_Wot[DD*ALLD];       // Wo^T half [n][k]
__device__ __half g_Qc [BB*HH*NN*DD];   // compacted Q [bh][j][d], pre-scaled
__device__ __half g_Kc [BB*HH*NN*DD];   // compacted K [bh][j][d]
__device__ __half g_Vtc[BB*HH*DD*NN];   // compacted V^T [bh][d][j]
__device__ __half g_Chc[BB*NN*ALLD];    // compacted ctx [b][j][ALLD]
__device__ int    g_idx[BB*NN];         // valid-token indices
__device__ int    g_cnt[BB];

__device__ __forceinline__ unsigned h2pack(float x, float y) {
    __half2 h = __floats2half2_rn(x, y);
    return *(unsigned*)&h;
}

__device__ __forceinline__ void mma16(float* c,
                                      unsigned a0, unsigned a1, unsigned a2, unsigned a3,
                                      unsigned b0, unsigned b1) {
    asm volatile(
        "mma.sync.aligned.m16n8k16.row.col.f32.f16.f16.f32 "
        "{%0,%1,%2,%3}, {%4,%5,%6,%7}, {%8,%9}, {%0,%1,%2,%3};"
        : "+f"(c[0]), "+f"(c[1]), "+f"(c[2]), "+f"(c[3])
        : "r"(a0), "r"(a1), "r"(a2), "r"(a3), "r"(b0), "r"(b1));
}

__device__ __forceinline__ void cp16(unsigned dst, const void* src) {
    asm volatile("cp.async.cg.shared.global [%0], [%1], 16;" :: "r"(dst), "l"(src));
}

#define SCQ 0.08838834764831845f   // 1/sqrt(128)

// ---------------------------------------------------------------------------
// Kernel 0: compact valid token indices per batch. grid BB, 256 threads.
// ---------------------------------------------------------------------------
__global__ __launch_bounds__(256)
void compact_kernel(const int* __restrict__ mask)
{
    __shared__ int cnts[256];
    __shared__ int offs[256];

    const int b = blockIdx.x;
    const int t = threadIdx.x;
    const int base = t * 8;

    int mloc[8];
    int c = 0;
    #pragma unroll
    for (int i = 0; i < 8; i++) {
        mloc[i] = mask[b * NN + base + i];
        c += (mloc[i] != 0);
    }
    cnts[t] = c;
    __syncthreads();

    if (t == 0) {
        int run = 0;
        for (int i = 0; i < 256; i++) { offs[i] = run; run += cnts[i]; }
        g_cnt[b] = run;
    }
    __syncthreads();

    int o = offs[t];
    #pragma unroll
    for (int i = 0; i < 8; i++)
        if (mloc[i]) g_idx[b * NN + (o++)] = base + i;

    __syncthreads();
    const int cnt = g_cnt[b];
    for (int i = cnt + t; i < NN; i += 256) g_idx[b * NN + i] = 0;
}

// ---------------------------------------------------------------------------
// Kernel 1a: gather x into compacted xc (half). grid N_XH/256.
// ---------------------------------------------------------------------------
#define N_XH (BN*DD)

__global__ __launch_bounds__(256)
void convert_x_kernel(const float* __restrict__ x)
{
    const int idx = blockIdx.x * 256 + threadIdx.x;
    const int r = idx >> 7;
    const int d = idx & 127;
    const int b = r >> 11;
    const int j = r & 2047;
    if (j < g_cnt[b])
        g_xc[idx] = __float2half_rn(
            x[((size_t)(b * NN + g_idx[b * NN + j])) * DD + d]);
}

// ---------------------------------------------------------------------------
// Kernel 1b: smem-tiled weight transpose to half (coalesced both ways).
// blocks 0..767:   Wq/Wk/Wv [128k x 2048c] -> g_Wt[c][k]  (SCQ folded in Wq)
// blocks 768..1023: Wo [2048k x 128n]      -> g_Wot[n][k]
// ---------------------------------------------------------------------------
__global__ __launch_bounds__(256)
void transpose_w_kernel(const float* __restrict__ Wq,
                        const float* __restrict__ Wk,
                        const float* __restrict__ Wv,
                        const float* __restrict__ Wo)
{
    __shared__ float ts[32][33];

    const int tid = blockIdx.x;
    const int tx  = threadIdx.x & 31;
    const int ty  = threadIdx.x >> 5;   // 0..7

    if (tid < 768) {
        const int proj = tid >> 8;
        const int tt   = tid & 255;
        const int k0   = (tt & 3) * 32;
        const int c0   = (tt >> 2) * 32;
        const float* W  = (proj == 0) ? Wq : (proj == 1) ? Wk : Wv;
        const float scl = (proj == 0) ? SCQ : 1.0f;
        #pragma unroll
        for (int i = 0; i < 4; i++) {
            const int row = ty + i * 8;
            ts[row][tx] = W[(size_t)(k0 + row) * ALLD + c0 + tx] * scl;
        }
        __syncthreads();
        #pragma unroll
        for (int i = 0; i < 4; i++) {
            const int r = ty + i * 8;
            g_Wt[(size_t)(proj * ALLD + c0 + r) * DD + k0 + tx] =
                __float2half_rn(ts[tx][r]);
        }
    } else {
        const int tt = tid - 768;
        const int n0 = (tt & 3) * 32;
        const int k0 = (tt >> 2) * 32;
        #pragma unroll
        for (int i = 0; i < 4; i++) {
            const int row = ty + i * 8;
            ts[row][tx] = Wo[(size_t)(k0 + row) * DD + n0 + tx];
        }
        __syncthreads();
        #pragma unroll
        for (int i = 0; i < 4; i++) {
            const int r = ty + i * 8;
            g_Wot[(size_t)(n0 + r) * ALLD + k0 + tx] =
                __float2half_rn(ts[tx][r]);
        }
    }
}

// ---------------------------------------------------------------------------
// Kernel 2: QKV projection over compacted rows (fp16 MMA).
// grid (BB*32, 48); block = 64 compacted rows x 128 cols; early exit.
// V output (proj==2) is transposed in-block and written to g_Vtc directly.
// (round-15 configuration)
// ---------------------------------------------------------------------------
#define GQ_XS_STR 136
#define GQ_XS_BYTES (64 * GQ_XS_STR * 2)
#define GQ_WS_BYTES (128 * GQ_XS_STR * 2)

__global__ __launch_bounds__(128)
void gemm_qkv_kernel(const float* __restrict__ bq,
                     const float* __restrict__ bk,
                     const float* __restrict__ bv)
{
    extern __shared__ char sm[];
    __half* xs = (__half*)sm;
    __half* ws = (__half*)(sm + GQ_XS_BYTES);

    const int b  = blockIdx.x >> 5;
    const int j0 = (blockIdx.x & 31) * 64;
    const int cnt = g_cnt[b];
    if (j0 >= cnt) return;

    const int n0 = blockIdx.y * 128;
    const int proj = n0 >> 11;
    const int h    = (n0 >> 7) & 15;

    const int t    = threadIdx.x;
    const int warp = t >> 5;
    const int lane = t & 31;
    const int g    = lane >> 2;
    const int tg   = lane & 3;
    const int m0   = warp * 16;

    const unsigned smu = (unsigned)__cvta_generic_to_shared(sm);

    #pragma unroll
    for (int p = 0; p < 8; p++) {
        const int c   = t + p * 128;
        const int row = c >> 4;
        const int cd  = (c & 15) * 8;
        cp16(smu + (row * GQ_XS_STR + cd) * 2,
             g_xc + ((size_t)(b * NN + j0 + row)) * DD + cd);
    }
    #pragma unroll
    for (int p = 0; p < 16; p++) {
        const int c   = t + p * 128;
        const int row = c >> 4;
        const int cd  = (c & 15) * 8;
        cp16(smu + GQ_XS_BYTES + (row * GQ_XS_STR + cd) * 2,
             g_Wt + (size_t)(n0 + row) * DD + cd);
    }
    asm volatile("cp.async.commit_group;" ::: "memory");
    asm volatile("cp.async.wait_group 0;" ::: "memory");
    __syncthreads();

    float acc[16][4];
    #pragma unroll
    for (int j = 0; j < 16; j++) { acc[j][0]=0.f; acc[j][1]=0.f; acc[j][2]=0.f; acc[j][3]=0.f; }

    #pragma unroll
    for (int s = 0; s < 8; s++) {
        const int kc = 16 * s + 2 * tg;
        const unsigned a0 = *(const unsigned*)&xs[(m0 + g)     * GQ_XS_STR + kc];
        const unsigned a1 = *(const unsigned*)&xs[(m0 + g + 8) * GQ_XS_STR + kc];
        const unsigned a2 = *(const unsigned*)&xs[(m0 + g)     * GQ_XS_STR + kc + 8];
        const unsigned a3 = *(const unsigned*)&xs[(m0 + g + 8) * GQ_XS_STR + kc + 8];
        #pragma unroll
        for (int j = 0; j < 16; j++) {
            const unsigned b0 = *(const unsigned*)&ws[(8 * j + g) * GQ_XS_STR + kc];
            const unsigned b1 = *(const unsigned*)&ws[(8 * j + g) * GQ_XS_STR + kc + 8];
            mma16(acc[j], a0, a1, a2, a3, b0, b1);
        }
    }

    const float* bias = (proj == 0) ? bq : (proj == 1) ? bk : bv;
    const int bcol = n0 & 2047;
    const int row0 = j0 + m0 + g;        // local compacted row
    const int row1 = row0 + 8;
    const int bh   = b * HH + h;

    if (proj < 2) {
        const float bscl = (proj == 0) ? SCQ : 1.0f;
        __half* dst = (proj == 0) ? g_Qc : g_Kc;
        __half* d0 = dst + ((size_t)bh * NN + row0) * DD;
        __half* d1 = dst + ((size_t)bh * NN + row1) * DD;
        const bool s0ok = row0 < cnt;
        const bool s1ok = row1 < cnt;

        #pragma unroll
        for (int j = 0; j < 16; j++) {
            const int ci = 8 * j + 2 * tg;
            const float bb0 = bias[bcol + ci]     * bscl;
            const float bb1 = bias[bcol + ci + 1] * bscl;
            if (s0ok) *(unsigned*)&d0[ci] = h2pack(acc[j][0] + bb0, acc[j][1] + bb1);
            if (s1ok) *(unsigned*)&d1[ci] = h2pack(acc[j][2] + bb0, acc[j][3] + bb1);
        }
    } else {
        // V: transpose in smem (reuse staging buffer), write Vtc directly.
        // Tail rows (>= cnt) come from zero xc -> acc = bias (finite); the
        // attention PV multiplies them by P==0, so unguarded writes are safe.
        __syncthreads();                  // all MMA smem reads complete
        __half* ts = (__half*)sm;         // [128 d][72]
        const int lr0 = m0 + g;
        const int lr1 = lr0 + 8;
        #pragma unroll
        for (int j = 0; j < 16; j++) {
            const int ci = 8 * j + 2 * tg;
            const float bb0 = bias[bcol + ci];
            const float bb1 = bias[bcol + ci + 1];
            ts[(ci    ) * VT_STR + lr0] = __float2half_rn(acc[j][0] + bb0);
            ts[(ci + 1) * VT_STR + lr0] = __float2half_rn(acc[j][1] + bb1);
            ts[(ci    ) * VT_STR + lr1] = __float2half_rn(acc[j][2] + bb0);
            ts[(ci + 1) * VT_STR + lr1] = __float2half_rn(acc[j][3] + bb1);
        }
        __syncthreads();

        const int d = t;                  // 0..127
        __half* dst = g_Vtc + ((size_t)bh * DD + d) * NN + j0;
        #pragma unroll
        for (int p = 0; p < 8; p++)
            *(uint4*)&dst[p * 8] = *(const uint4*)&ts[d * VT_STR + p * 8];
    }
}

// ---------------------------------------------------------------------------
// Kernel 4: flash attention over compacted q/k/v. 3 blocks/SM enforced.
// (unchanged from round 15)
// ---------------------------------------------------------------------------
#define KS_BYTES (TK * KS_STR * 2)
#define VT_BYTES (DD * VT_STR * 2)
#define SM_KS(buf)  ((buf) * KS_BYTES)
#define SM_VT(buf)  (2 * KS_BYTES + (buf) * VT_BYTES)
#define ATT_SMEM    (2 * KS_BYTES + 2 * VT_BYTES)

__global__ __launch_bounds__(128, 3)
void attn_fp16_kernel()
{
    extern __shared__ char sm[];

    const int bid = blockIdx.x;
    const int qt  = bid & 31;
    const int bh  = bid >> 5;
    const int b   = bh >> 4;
    const int n0  = qt * BQ;

    const int cnt = g_cnt[b];
    if (n0 >= cnt) return;

    const int t    = threadIdx.x;
    const int warp = t >> 5;
    const int lane = t & 31;
    const int g    = lane >> 2;
    const int tg   = lane & 3;
    const int m0   = warp * 16;

    const __half* Qc  = g_Qc  + (size_t)bh * NN * DD;
    const __half* Kc  = g_Kc  + (size_t)bh * NN * DD;
    const __half* Vtc = g_Vtc + (size_t)bh * DD * NN;

    const unsigned smu = (unsigned)__cvta_generic_to_shared(sm);

    auto stage = [&](int kt, int buf) {
        const int k0 = kt * TK;
        const unsigned ksu = smu + SM_KS(buf);
        const unsigned vtu = smu + SM_VT(buf);
        #pragma unroll
        for (int p = 0; p < 8; p++) {
            const int c   = t + p * 128;
            const int row = c >> 4;
            const int cd  = (c & 15) * 8;
            cp16(ksu + (row * KS_STR + cd) * 2, Kc + (size_t)(k0 + row) * DD + cd);
        }
        #pragma unroll
        for (int p = 0; p < 8; p++) {
            const int c   = t + p * 128;
            const int row = c >> 3;
            const int cd  = (c & 7) * 8;
            cp16(vtu + (row * VT_STR + cd) * 2, Vtc + (size_t)row * NN + k0 + cd);
        }
        asm volatile("cp.async.commit_group;" ::: "memory");
    };

    const int jr0 = n0 + m0 + g;
    const int jr1 = jr0 + 8;
    unsigned qa[8][4];
    {
        const __half* q0 = Qc + (size_t)jr0 * DD;
        const __half* q1 = Qc + (size_t)jr1 * DD;
        #pragma unroll
        for (int s = 0; s < 8; s++) {
            const int c = 16 * s + 2 * tg;
            qa[s][0] = *(const unsigned*)&q0[c];
            qa[s][1] = *(const unsigned*)&q1[c];
            qa[s][2] = *(const unsigned*)&q0[c + 8];
            qa[s][3] = *(const unsigned*)&q1[c + 8];
        }
    }

    const int NTc = (cnt + TK - 1) / TK;
    stage(0, 0);

    float o[16][4];
    #pragma unroll
    for (int j = 0; j < 16; j++) { o[j][0]=0.f; o[j][1]=0.f; o[j][2]=0.f; o[j][3]=0.f; }
    float l0 = 0.f, l1 = 0.f;

    for (int kt = 0; kt < NTc; kt++) {
        const int buf = kt & 1;
        const int k0  = kt * TK;
        asm volatile("cp.async.wait_group 0;" ::: "memory");
        __syncthreads();

        if (kt + 1 < NTc) stage(kt + 1, buf ^ 1);

        const __half* ks = (const __half*)(sm + SM_KS(buf));
        const __half* vt = (const __half*)(sm + SM_VT(buf));

        float sc[8][4];
        #pragma unroll
        for (int j = 0; j < 8; j++) { sc[j][0]=0.f; sc[j][1]=0.f; sc[j][2]=0.f; sc[j][3]=0.f; }

        #pragma unroll
        for (int s = 0; s < 8; s++) {
            const int dcol = 16 * s + 2 * tg;
            #pragma unroll
            for (int j = 0; j < 8; j++) {
                const unsigned b0 = *(const unsigned*)&ks[(8 * j + g) * KS_STR + dcol];
                const unsigned b1 = *(const unsigned*)&ks[(8 * j + g) * KS_STR + dcol + 8];
                mma16(sc[j], qa[s][0], qa[s][1], qa[s][2], qa[s][3], b0, b1);
            }
        }

        unsigned pa[4][4];
        #pragma unroll
        for (int j = 0; j < 8; j++) {
            const int ci = 8 * j + 2 * tg;
            const bool v0 = (k0 + ci)     < cnt;
            const bool v1 = (k0 + ci + 1) < cnt;
            const float e0 = v0 ? __expf(sc[j][0]) : 0.f;
            const float e1 = v1 ? __expf(sc[j][1]) : 0.f;
            const float e2 = v0 ? __expf(sc[j][2]) : 0.f;
            const float e3 = v1 ? __expf(sc[j][3]) : 0.f;
            l0 += e0 + e1;
            l1 += e2 + e3;
            const unsigned h01 = h2pack(e0, e1);
            const unsigned h23 = h2pack(e2, e3);
            const int s2 = j >> 1;
            if ((j & 1) == 0) { pa[s2][0] = h01; pa[s2][1] = h23; }
            else              { pa[s2][2] = h01; pa[s2][3] = h23; }
        }

        #pragma unroll
        for (int s2 = 0; s2 < 4; s2++) {
            const int kcol = 16 * s2 + 2 * tg;
            #pragma unroll
            for (int j2 = 0; j2 < 16; j2++) {
                const unsigned b0 = *(const unsigned*)&vt[(8 * j2 + g) * VT_STR + kcol];
                const unsigned b1 = *(const unsigned*)&vt[(8 * j2 + g) * VT_STR + kcol + 8];
                mma16(o[j2], pa[s2][0], pa[s2][1], pa[s2][2], pa[s2][3], b0, b1);
            }
        }
        __syncthreads();
    }

    l0 += __shfl_xor_sync(0xffffffffu, l0, 1);
    l0 += __shfl_xor_sync(0xffffffffu, l0, 2);
    l1 += __shfl_xor_sync(0xffffffffu, l1, 1);
    l1 += __shfl_xor_sync(0xffffffffu, l1, 2);

    const bool  val0 = jr0 < cnt;
    const bool  val1 = jr1 < cnt;
    const float inv0 = 1.0f / l0;
    const float inv1 = 1.0f / l1;
    const int   h    = bh & 15;

    __half* ctx0 = g_Chc + ((size_t)(b * NN + jr0)) * ALLD + h * DD;
    __half* ctx1 = g_Chc + ((size_t)(b * NN + jr1)) * ALLD + h * DD;
    #pragma unroll
    for (int j2 = 0; j2 < 16; j2++) {
        const int ci = 8 * j2 + 2 * tg;
        if (val0) *(unsigned*)&ctx0[ci] = h2pack(o[j2][0] * inv0, o[j2][1] * inv0);
        if (val1) *(unsigned*)&ctx1[ci] = h2pack(o[j2][2] * inv1, o[j2][3] * inv1);
    }
}

// ---------------------------------------------------------------------------
// Kernel 5: output projection over compacted ctx rows; scatter via idx.
// grid (BB*64); block = 32 compacted rows; early exit. (round-15 config)
// ---------------------------------------------------------------------------
#define GO_AS_STR 72
#define GO_AS_BYTES (32 * GO_AS_STR * 2)
#define GO_WS_BYTES (128 * GO_AS_STR * 2)
#define GO_SM_A(buf) ((buf) * (GO_AS_BYTES + GO_WS_BYTES))
#define GO_SM_W(buf) (GO_SM_A(buf) + GO_AS_BYTES)
#define GO_SMEM (2 * (GO_AS_BYTES + GO_WS_BYTES))

__global__ __launch_bounds__(128)
void gemm_out_kernel(const float* __restrict__ bo, float* __restrict__ out)
{
    extern __shared__ char sm[];

    const int b   = blockIdx.x >> 6;
    const int r0c = (blockIdx.x & 63) * 32;
    const int cnt = g_cnt[b];
    if (r0c >= cnt) return;

    const int t    = threadIdx.x;
    const int warp = t >> 5;
    const int lane = t & 31;
    const int g    = lane >> 2;
    const int tg   = lane & 3;

    const unsigned smu = (unsigned)__cvta_generic_to_shared(sm);
    const __half* A = g_Chc + (size_t)(b * NN + r0c) * ALLD;

    auto stage = [&](int kt, int buf) {
        const int k0 = kt * 64;
        const unsigned au = smu + GO_SM_A(buf);
        const unsigned wu = smu + GO_SM_W(buf);
        #pragma unroll
        for (int p = 0; p < 2; p++) {
            const int c   = t + p * 128;
            const int row = c >> 3;
            const int cd  = (c & 7) * 8;
            cp16(au + (row * GO_AS_STR + cd) * 2, A + (size_t)row * ALLD + k0 + cd);
        }
        #pragma unroll
        for (int p = 0; p < 8; p++) {
            const int c   = t + p * 128;
            const int row = c >> 3;
            const int cd  = (c & 7) * 8;
            cp16(wu + (row * GO_AS_STR + cd) * 2, g_Wot + (size_t)row * ALLD + k0 + cd);
        }
        asm volatile("cp.async.commit_group;" ::: "memory");
    };

    stage(0, 0);

    float acc[2][4][4];
    #pragma unroll
    for (int jm = 0; jm < 2; jm++)
        #pragma unroll
        for (int jn = 0; jn < 4; jn++) {
            acc[jm][jn][0]=0.f; acc[jm][jn][1]=0.f; acc[jm][jn][2]=0.f; acc[jm][jn][3]=0.f;
        }

    for (int kt = 0; kt < 32; kt++) {
        const int buf = kt & 1;
        asm volatile("cp.async.wait_group 0;" ::: "memory");
        __syncthreads();

        if (kt + 1 < 32) stage(kt + 1, buf ^ 1);

        const __half* as = (const __half*)(sm + GO_SM_A(buf));
        const __half* ws = (const __half*)(sm + GO_SM_W(buf));

        #pragma unroll
        for (int s = 0; s < 4; s++) {
            const int kc = 16 * s + 2 * tg;
            unsigned a[2][4];
            #pragma unroll
            for (int jm = 0; jm < 2; jm++) {
                a[jm][0] = *(const unsigned*)&as[(16 * jm + g)     * GO_AS_STR + kc];
                a[jm][1] = *(const unsigned*)&as[(16 * jm + g + 8) * GO_AS_STR + kc];
                a[jm][2] = *(const unsigned*)&as[(16 * jm + g)     * GO_AS_STR + kc + 8];
                a[jm][3] = *(const unsigned*)&as[(16 * jm + g + 8) * GO_AS_STR + kc + 8];
            }
            #pragma unroll
            for (int jn = 0; jn < 4; jn++) {
                const int n = 32 * warp + 8 * jn + g;
                const unsigned b0 = *(const unsigned*)&ws[n * GO_AS_STR + kc];
                const unsigned b1 = *(const unsigned*)&ws[n * GO_AS_STR + kc + 8];
                #pragma unroll
                for (int jm = 0; jm < 2; jm++)
                    mma16(acc[jm][jn], a[jm][0], a[jm][1], a[jm][2], a[jm][3], b0, b1);
            }
        }
        __syncthreads();
    }

    const int* idx = g_idx + b * NN;
    #pragma unroll
    for (int jm = 0; jm < 2; jm++) {
        const int jrow0 = r0c + 16 * jm + g;
        const int jrow1 = jrow0 + 8;
        const bool ok0 = jrow0 < cnt;
        const bool ok1 = jrow1 < cnt;
        const int orow0 = ok0 ? (b * NN + idx[jrow0]) : 0;
        const int orow1 = ok1 ? (b * NN + idx[jrow1]) : 0;
        #pragma unroll
        for (int jn = 0; jn < 4; jn++) {
            const int col = 32 * warp + 8 * jn + 2 * tg;
            const float bb0 = bo[col], bb1 = bo[col + 1];
            float2 w0, w1;
            w0.x = acc[jm][jn][0] + bb0;  w0.y = acc[jm][jn][1] + bb1;
            w1.x = acc[jm][jn][2] + bb0;  w1.y = acc[jm][jn][3] + bb1;
            if (ok0) *(float2*)&out[(size_t)orow0 * DD + col] = w0;
            if (ok1) *(float2*)&out[(size_t)orow1 * DD + col] = w1;
        }
    }
}

// ---------------------------------------------------------------------------
// Kernel 6: fill masked output rows with bias. grid 512, 256 thr.
// ---------------------------------------------------------------------------
__global__ __launch_bounds__(256)
void fill_out_kernel(const int* __restrict__ mask,
                     const float* __restrict__ bo,
                     float* __restrict__ out)
{
    const int i = blockIdx.x * 256 + threadIdx.x;
    const int total = BN * DD;
    for (int idx = i; idx < total; idx += gridDim.x * 256) {
        const int row = idx >> 7;
        if (mask[row] == 0)
            out[idx] = __ldg(&bo[idx & 127]);
    }
}

// ---------------------------------------------------------------------------
extern "C" void kernel_launch(void* const* d_in, const int* in_sizes, int n_in,
                              void* d_out, int out_size)
{
    const float* x    = (const float*)d_in[0];
    const int*   mask = (const int*)  d_in[1];
    const float* Wq   = (const float*)d_in[2];
    const float* bq   = (const float*)d_in[3];
    const float* Wk   = (const float*)d_in[4];
    const float* bk   = (const float*)d_in[5];
    const float* Wv   = (const float*)d_in[6];
    const float* bv   = (const float*)d_in[7];
    const float* Wo   = (const float*)d_in[8];
    const float* bo   = (const float*)d_in[9];
    float* out = (float*)d_out;

    compact_kernel<<<BB, 256>>>(mask);
    convert_x_kernel<<<N_XH / 256, 256>>>(x);
    transpose_w_kernel<<<1024, 256>>>(Wq, Wk, Wv, Wo);

    cudaFuncSetAttribute((const void*)gemm_qkv_kernel,
                         cudaFuncAttributeMaxDynamicSharedMemorySize,
                         GQ_XS_BYTES + GQ_WS_BYTES);
    gemm_qkv_kernel<<<dim3(BB * 32, 48), 128, GQ_XS_BYTES + GQ_WS_BYTES>>>(bq, bk, bv);

    cudaFuncSetAttribute((const void*)attn_fp16_kernel,
                         cudaFuncAttributeMaxDynamicSharedMemorySize, ATT_SMEM);
    attn_fp16_kernel<<<BB * HH * 32, 128, ATT_SMEM>>>();

    cudaFuncSetAttribute((const void*)gemm_out_kernel,
                         cudaFuncAttributeMaxDynamicSharedMemorySize, GO_SMEM);
    gemm_out_kernel<<<BB * 64, 128, GO_SMEM>>>(bo, out);

    fill_out_kernel<<<512, 256>>>(mask, bo, out);
}